// round 2
// baseline (speedup 1.0000x reference)
#include <cuda_runtime.h>

// ---------------------------------------------------------------------------
// UMT5 encoder self-attention, fp32 baseline.
// Outputs: d_out[0 .. 4194304)              = attn_output [B,S,D]
//          d_out[4194304 .. 138412032)      = attn        [B,H,S,S]
// ---------------------------------------------------------------------------

#define kB  2
#define kS  2048
#define kD  1024
#define kH  16
#define kDK 64
#define kBH (kB * kH)
#define kNB (2 * kS - 1)          // 4095 relative-position deltas
#define kOUT0 ((long long)kB * kS * kD)   // 4194304

// Scratch (static device globals; no allocations anywhere)
__device__ float g_q[kBH * kS * kDK];
__device__ float g_k[kBH * kS * kDK];
__device__ float g_v[kBH * kS * kDK];
__device__ float g_ctx[kB * kS * kD];
__device__ float g_bias[kH * kNB];

// ---------------------------------------------------------------------------
// Bias table: g_bias[h][delta+2047] = rel_bias[bucket(delta)][h]
// Bucket boundaries done in integer arithmetic (matches correctly-rounded
// float32 reference exactly; boundaries at |d|=16,32,64 are exact in fp32).
// ---------------------------------------------------------------------------
__global__ void bias_kernel(const float* __restrict__ rel_bias) {
    int idx = blockIdx.x * blockDim.x + threadIdx.x;
    if (idx >= kH * kNB) return;
    int h = idx / kNB;
    int delta = idx % kNB - (kS - 1);
    int bucket = (delta > 0) ? 16 : 0;
    int a = delta < 0 ? -delta : delta;
    int add;
    if (a < 8)       add = a;
    else if (a < 12) add = 8;
    else if (a < 16) add = 9;
    else if (a < 23) add = 10;
    else if (a < 32) add = 11;
    else if (a < 46) add = 12;
    else if (a < 64) add = 13;
    else if (a < 91) add = 14;
    else             add = 15;
    bucket += add;
    g_bias[idx] = rel_bias[bucket * kH + h];
}

// ---------------------------------------------------------------------------
// SGEMM: C[4096x1024] = A[4096x1024] * W[1024x1024], fp32.
// BM=BN=64, BK=16, 256 threads, 4x4 micro-tile.
// scatter=1: write to [bh][s][dk] layout (QKV). scatter=0: row-major.
// ---------------------------------------------------------------------------
__global__ void __launch_bounds__(256) sgemm_kernel(
    const float* __restrict__ A, const float* __restrict__ W,
    float* __restrict__ C, int scatter)
{
    __shared__ float As[16][64];   // [k][m]
    __shared__ float Bs[16][64];   // [k][n]
    const int tid = threadIdx.x;
    const int tn = tid & 15, tm = tid >> 4;
    const int mBase = blockIdx.y * 64;
    const int nBase = blockIdx.x * 64;
    const int la_m = tid >> 2;
    const int la_k = (tid & 3) * 4;
    const int lb_k = tid >> 4;
    const int lb_n = (tid & 15) * 4;
    float acc[4][4] = {};

    for (int k0 = 0; k0 < kD; k0 += 16) {
        float4 av = *(const float4*)(A + (size_t)(mBase + la_m) * kD + k0 + la_k);
        float4 bv = *(const float4*)(W + (size_t)(k0 + lb_k) * kD + nBase + lb_n);
        As[la_k + 0][la_m] = av.x;
        As[la_k + 1][la_m] = av.y;
        As[la_k + 2][la_m] = av.z;
        As[la_k + 3][la_m] = av.w;
        *(float4*)&Bs[lb_k][lb_n] = bv;
        __syncthreads();
#pragma unroll
        for (int kk = 0; kk < 16; kk++) {
            float4 a = *(const float4*)&As[kk][tm * 4];
            float4 b = *(const float4*)&Bs[kk][tn * 4];
            float ar[4] = {a.x, a.y, a.z, a.w};
            float br[4] = {b.x, b.y, b.z, b.w};
#pragma unroll
            for (int i = 0; i < 4; i++)
#pragma unroll
                for (int j = 0; j < 4; j++)
                    acc[i][j] = fmaf(ar[i], br[j], acc[i][j]);
        }
        __syncthreads();
    }

    if (!scatter) {
#pragma unroll
        for (int i = 0; i < 4; i++) {
            int row = mBase + tm * 4 + i;
            *(float4*)(C + (size_t)row * kD + nBase + tn * 4) =
                make_float4(acc[i][0], acc[i][1], acc[i][2], acc[i][3]);
        }
    } else {
        int h = nBase >> 6;        // nBase is a multiple of 64
        int dk = tn * 4;
#pragma unroll
        for (int i = 0; i < 4; i++) {
            int row = mBase + tm * 4 + i;
            int b = row >> 11, s = row & (kS - 1);
            size_t dst = ((size_t)(b * kH + h) * kS + s) * kDK + dk;
            *(float4*)(C + dst) =
                make_float4(acc[i][0], acc[i][1], acc[i][2], acc[i][3]);
        }
    }
}

// ---------------------------------------------------------------------------
// Attention: per block = one (bh, 64-row q-tile).
// Phase 1: logits = QK^T + bias, online max/sum, raw logits -> attn buffer.
// Phase 2: normalize in place (final attn), accumulate ctx = P*V.
// All smem tiles natural layout, stride 68 (conflict-free / broadcast LDS).
// ---------------------------------------------------------------------------
__global__ void __launch_bounds__(256) attn_kernel(float* __restrict__ attn) {
    __shared__ float Pa[64][68];   // Q tile, then P tile  [m][d]/[m][k]
    __shared__ float Pb[64][68];   // K tile, then V tile  [n][d]/[k][d]
    __shared__ float Ms[64], Ls[64], Li[64];
    __shared__ float bias_s[128];

    const int bh = blockIdx.y;
    const int h = bh & (kH - 1);
    const int q0 = blockIdx.x * 64;
    const int tid = threadIdx.x;
    const int tn = tid & 15, tm = tid >> 4;

    const float* Qp = g_q + (size_t)bh * kS * kDK + (size_t)q0 * kDK;
    const float* Kp = g_k + (size_t)bh * kS * kDK;
    const float* Vp = g_v + (size_t)bh * kS * kDK;
    float* Ap = attn + (size_t)bh * kS * kS;

    // Load Q tile [64][64]
    {
        const float4* src = (const float4*)Qp;
#pragma unroll
        for (int r = 0; r < 4; r++) {
            int f4 = r * 256 + tid;
            int m = f4 >> 4;
            int d4 = (f4 & 15) << 2;
            *(float4*)&Pa[m][d4] = src[f4];
        }
    }
    if (tid < 64) { Ms[tid] = -3.0e38f; Ls[tid] = 0.0f; }
    __syncthreads();

    // ---------------- Phase 1 ----------------
    for (int kt = 0; kt < kS / 64; kt++) {
        {
            const float4* src = (const float4*)(Kp + (size_t)kt * 64 * kDK);
#pragma unroll
            for (int r = 0; r < 4; r++) {
                int f4 = r * 256 + tid;
                int m = f4 >> 4;
                int d4 = (f4 & 15) << 2;
                *(float4*)&Pb[m][d4] = src[f4];
            }
        }
        if (tid < 127)
            bias_s[tid] = g_bias[h * kNB + (kt * 64 - q0) + tid - 63 + (kS - 1)];
        __syncthreads();

        float sc[4][4] = {};
#pragma unroll
        for (int d4 = 0; d4 < 64; d4 += 4) {
            float4 qa[4], kb[4];
#pragma unroll
            for (int i = 0; i < 4; i++) qa[i] = *(const float4*)&Pa[tm * 4 + i][d4];
#pragma unroll
            for (int j = 0; j < 4; j++) kb[j] = *(const float4*)&Pb[tn * 4 + j][d4];
#pragma unroll
            for (int i = 0; i < 4; i++)
#pragma unroll
                for (int j = 0; j < 4; j++) {
                    sc[i][j] = fmaf(qa[i].x, kb[j].x, sc[i][j]);
                    sc[i][j] = fmaf(qa[i].y, kb[j].y, sc[i][j]);
                    sc[i][j] = fmaf(qa[i].z, kb[j].z, sc[i][j]);
                    sc[i][j] = fmaf(qa[i].w, kb[j].w, sc[i][j]);
                }
        }

#pragma unroll
        for (int i = 0; i < 4; i++) {
            int row = tm * 4 + i;
#pragma unroll
            for (int j = 0; j < 4; j++)
                sc[i][j] += bias_s[tn * 4 + j - row + 63];
            float mx = fmaxf(fmaxf(sc[i][0], sc[i][1]), fmaxf(sc[i][2], sc[i][3]));
#pragma unroll
            for (int off = 8; off; off >>= 1)
                mx = fmaxf(mx, __shfl_xor_sync(0xffffffffu, mx, off));
            float mo = Ms[row];
            float mn = fmaxf(mo, mx);
            float ps = __expf(sc[i][0] - mn) + __expf(sc[i][1] - mn)
                     + __expf(sc[i][2] - mn) + __expf(sc[i][3] - mn);
#pragma unroll
            for (int off = 8; off; off >>= 1)
                ps += __shfl_xor_sync(0xffffffffu, ps, off);
            if (tn == 0) {
                Ms[row] = mn;
                Ls[row] = Ls[row] * __expf(mo - mn) + ps;
            }
            // raw logits (re-read in phase 2, then overwritten with attn)
            *(float4*)&Ap[(size_t)(q0 + row) * kS + kt * 64 + tn * 4] =
                make_float4(sc[i][0], sc[i][1], sc[i][2], sc[i][3]);
        }
        __syncthreads();
    }

    if (tid < 64) Li[tid] = 1.0f / Ls[tid];
    __syncthreads();

    // ---------------- Phase 2 ----------------
    float acc[4][4] = {};
    for (int kt = 0; kt < kS / 64; kt++) {
        {
            const float4* src = (const float4*)(Vp + (size_t)kt * 64 * kDK);
#pragma unroll
            for (int r = 0; r < 4; r++) {
                int f4 = r * 256 + tid;
                int m = f4 >> 4;
                int d4 = (f4 & 15) << 2;
                *(float4*)&Pb[m][d4] = src[f4];
            }
        }
#pragma unroll
        for (int r = 0; r < 4; r++) {
            int f4 = r * 256 + tid;
            int m = f4 >> 4;
            int c4 = (f4 & 15) << 2;
            size_t gi = (size_t)(q0 + m) * kS + kt * 64 + c4;
            float4 v = *(const float4*)&Ap[gi];
            float mrow = Ms[m], li = Li[m];
            v.x = __expf(v.x - mrow) * li;
            v.y = __expf(v.y - mrow) * li;
            v.z = __expf(v.z - mrow) * li;
            v.w = __expf(v.w - mrow) * li;
            *(float4*)&Ap[gi] = v;          // final attn output
            *(float4*)&Pa[m][c4] = v;       // P tile [m][k]
        }
        __syncthreads();

#pragma unroll 16
        for (int kk = 0; kk < 64; kk++) {
            float4 vb = *(const float4*)&Pb[kk][tn * 4];
            float av[4];
#pragma unroll
            for (int i = 0; i < 4; i++) av[i] = Pa[tm * 4 + i][kk];
            float br[4] = {vb.x, vb.y, vb.z, vb.w};
#pragma unroll
            for (int i = 0; i < 4; i++)
#pragma unroll
                for (int j = 0; j < 4; j++)
                    acc[i][j] = fmaf(av[i], br[j], acc[i][j]);
        }
        __syncthreads();
    }

    // ctx -> [B,S,H*DK] row-major for the output projection
    const int b = bh >> 4;
#pragma unroll
    for (int i = 0; i < 4; i++) {
        int srow = q0 + tm * 4 + i;
        *(float4*)&g_ctx[(size_t)(b * kS + srow) * kD + h * kDK + tn * 4] =
            make_float4(acc[i][0], acc[i][1], acc[i][2], acc[i][3]);
    }
}

// ---------------------------------------------------------------------------
extern "C" void kernel_launch(void* const* d_in, const int* in_sizes, int n_in,
                              void* d_out, int out_size) {
    const float* hidden = (const float*)d_in[0];
    const float* wq     = (const float*)d_in[1];
    const float* wk     = (const float*)d_in[2];
    const float* wv     = (const float*)d_in[3];
    const float* wo     = (const float*)d_in[4];
    const float* rb     = (const float*)d_in[5];
    float* out  = (float*)d_out;
    float* attn = out + kOUT0;

    float *qp, *kp, *vp, *cp;
    cudaGetSymbolAddress((void**)&qp, g_q);
    cudaGetSymbolAddress((void**)&kp, g_k);
    cudaGetSymbolAddress((void**)&vp, g_v);
    cudaGetSymbolAddress((void**)&cp, g_ctx);

    bias_kernel<<<(kH * kNB + 255) / 256, 256>>>(rb);

    dim3 gg(kD / 64, (kB * kS) / 64);
    sgemm_kernel<<<gg, 256>>>(hidden, wq, qp, 1);
    sgemm_kernel<<<gg, 256>>>(hidden, wk, kp, 1);
    sgemm_kernel<<<gg, 256>>>(hidden, wv, vp, 1);

    attn_kernel<<<dim3(kS / 64, kBH), 256>>>(attn);

    sgemm_kernel<<<gg, 256>>>(cp, wo, out, 0);
}

// round 6
// speedup vs baseline: 2.4278x; 2.4278x over previous
#include <cuda_runtime.h>
#include <cuda_bf16.h>
#include <cstdint>

#define kB 2
#define kS 2048
#define kD 1024
#define kH 16
#define kDK 64
#define kBH 32
#define kNB 4095
#define kM 4096
#define kOUT0 4194304LL
#define SA 88      // smem row stride in bf16 elems (176B: 16B-aligned, ldmatrix conflict-free)

// ---------------- device scratch (no allocations anywhere) ----------------
__device__ __nv_bfloat16 g_xhi[kM*kD], g_xlo[kM*kD];
__device__ __nv_bfloat16 g_wqhi[kD*kD], g_wqlo[kD*kD];
__device__ __nv_bfloat16 g_wkhi[kD*kD], g_wklo[kD*kD];
__device__ __nv_bfloat16 g_wvhi[kD*kD], g_wvlo[kD*kD];
__device__ __nv_bfloat16 g_wohi[kD*kD], g_wolo[kD*kD];
__device__ __nv_bfloat16 g_qhi[kM*kD],  g_qlo[kM*kD];
__device__ __nv_bfloat16 g_khi[kM*kD],  g_klo[kM*kD];
__device__ __nv_bfloat16 g_vhi[kM*kD],  g_vlo[kM*kD];
__device__ __nv_bfloat16 g_vthi[kBH*kDK*kS], g_vtlo[kBH*kDK*kS];
__device__ __nv_bfloat16 g_chi[kM*kD],  g_clo[kM*kD];
__device__ float g_bias[kH*kNB];

// ---------------- PTX helpers (base sm_80-level features only) ----------------
__device__ __forceinline__ uint32_t smem_u32(const void* p){
    uint32_t a;
    asm("{ .reg .u64 t; cvta.to.shared.u64 t, %1; cvt.u32.u64 %0, t; }" : "=r"(a) : "l"(p));
    return a;
}
__device__ __forceinline__ void ldsm4(uint32_t* r, uint32_t addr){
    asm volatile("ldmatrix.sync.aligned.m8n8.x4.shared.b16 {%0,%1,%2,%3}, [%4];"
        : "=r"(r[0]),"=r"(r[1]),"=r"(r[2]),"=r"(r[3]) : "r"(addr));
}
__device__ __forceinline__ void mma16816(float* c, const uint32_t* a, const uint32_t* b){
    asm volatile("mma.sync.aligned.m16n8k16.row.col.f32.bf16.bf16.f32 "
        "{%0,%1,%2,%3}, {%4,%5,%6,%7}, {%8,%9}, {%0,%1,%2,%3};"
        : "+f"(c[0]),"+f"(c[1]),"+f"(c[2]),"+f"(c[3])
        : "r"(a[0]),"r"(a[1]),"r"(a[2]),"r"(a[3]), "r"(b[0]),"r"(b[1]));
}
__device__ __forceinline__ void cp16(uint32_t dst, const void* src){
    asm volatile("cp.async.cg.shared.global [%0], [%1], 16;" :: "r"(dst), "l"(src));
}
__device__ __forceinline__ void cp_commit(){ asm volatile("cp.async.commit_group;" ::: "memory"); }
template<int N> __device__ __forceinline__ void cp_wait(){
    asm volatile("cp.async.wait_group %0;" :: "n"(N) : "memory");
}

// ---------------- small prep kernels ----------------
__global__ void bias_kernel(const float* __restrict__ rel_bias){
    int idx = blockIdx.x*blockDim.x + threadIdx.x;
    if (idx >= kH*kNB) return;
    int h = idx / kNB;
    int delta = idx % kNB - (kS-1);
    int bucket = (delta > 0) ? 16 : 0;
    int a = delta < 0 ? -delta : delta;
    int add;
    if      (a < 8)  add = a;
    else if (a < 12) add = 8;
    else if (a < 16) add = 9;
    else if (a < 23) add = 10;
    else if (a < 32) add = 11;
    else if (a < 46) add = 12;
    else if (a < 64) add = 13;
    else if (a < 91) add = 14;
    else             add = 15;
    g_bias[idx] = rel_bias[(bucket + add)*kH + h];
}

__global__ void convert_x_kernel(const float* __restrict__ x){
    int i = blockIdx.x*256 + threadIdx.x;
    float v = x[i];
    __nv_bfloat16 h = __float2bfloat16(v);
    g_xhi[i] = h;
    g_xlo[i] = __float2bfloat16(v - __bfloat162float(h));
}

__global__ void transpose_split_kernel(const float* __restrict__ W,
                                       __nv_bfloat16* __restrict__ Thi,
                                       __nv_bfloat16* __restrict__ Tlo){
    __shared__ float t[32][33];
    int x = blockIdx.x*32 + threadIdx.x;
    int y0 = blockIdx.y*32;
#pragma unroll
    for (int j = 0; j < 32; j += 8)
        t[threadIdx.y+j][threadIdx.x] = W[(size_t)(y0+threadIdx.y+j)*kD + x];
    __syncthreads();
    int n0 = blockIdx.x*32;
#pragma unroll
    for (int j = 0; j < 32; j += 8){
        float v = t[threadIdx.x][threadIdx.y+j];
        size_t o = (size_t)(n0+threadIdx.y+j)*kD + y0 + threadIdx.x;
        __nv_bfloat16 h = __float2bfloat16(v);
        Thi[o] = h;
        Tlo[o] = __float2bfloat16(v - __bfloat162float(h));
    }
}

// V [row=b*2048+s][col=h*64+dk] pair -> Vt [bh][dk][s] pair
__global__ void transpose_v_kernel(){
    __shared__ __nv_bfloat16 th[32][33], tl[32][33];
    int bh = blockIdx.z, b = bh >> 4, h = bh & 15;
    int s0 = blockIdx.x*32, d0 = blockIdx.y*32;
#pragma unroll
    for (int j = 0; j < 32; j += 8){
        size_t src = (size_t)(b*kS + s0 + threadIdx.y + j)*kD + h*kDK + d0 + threadIdx.x;
        th[threadIdx.y+j][threadIdx.x] = g_vhi[src];
        tl[threadIdx.y+j][threadIdx.x] = g_vlo[src];
    }
    __syncthreads();
#pragma unroll
    for (int j = 0; j < 32; j += 8){
        size_t dst = ((size_t)bh*kDK + d0 + threadIdx.y + j)*kS + s0 + threadIdx.x;
        g_vthi[dst] = th[threadIdx.x][threadIdx.y+j];
        g_vtlo[dst] = tl[threadIdx.x][threadIdx.y+j];
    }
}

// ---------------- softmax over logit rows (in place) ----------------
__global__ void __launch_bounds__(256) softmax_kernel(float* __restrict__ attn){
    __shared__ float red[8];
    float* p = attn + (size_t)blockIdx.x * kS;
    int tid = threadIdx.x, wid = tid >> 5, lid = tid & 31;
    float4 v0 = ((const float4*)p)[tid];
    float4 v1 = ((const float4*)p)[tid + 256];
    float m = fmaxf(fmaxf(fmaxf(v0.x,v0.y), fmaxf(v0.z,v0.w)),
                    fmaxf(fmaxf(v1.x,v1.y), fmaxf(v1.z,v1.w)));
#pragma unroll
    for (int o = 16; o; o >>= 1) m = fmaxf(m, __shfl_xor_sync(~0u, m, o));
    if (lid == 0) red[wid] = m;
    __syncthreads();
    m = red[0];
#pragma unroll
    for (int i = 1; i < 8; i++) m = fmaxf(m, red[i]);
    v0.x = __expf(v0.x-m); v0.y = __expf(v0.y-m); v0.z = __expf(v0.z-m); v0.w = __expf(v0.w-m);
    v1.x = __expf(v1.x-m); v1.y = __expf(v1.y-m); v1.z = __expf(v1.z-m); v1.w = __expf(v1.w-m);
    float s = v0.x+v0.y+v0.z+v0.w + v1.x+v1.y+v1.z+v1.w;
#pragma unroll
    for (int o = 16; o; o >>= 1) s += __shfl_xor_sync(~0u, s, o);
    __syncthreads();
    if (lid == 0) red[wid] = s;
    __syncthreads();
    s = red[0];
#pragma unroll
    for (int i = 1; i < 8; i++) s += red[i];
    float inv = 1.0f / s;
    v0.x*=inv; v0.y*=inv; v0.z*=inv; v0.w*=inv;
    v1.x*=inv; v1.y*=inv; v1.z*=inv; v1.w*=inv;
    ((float4*)p)[tid] = v0;
    ((float4*)p)[tid + 256] = v1;
}

// ---------------------------------------------------------------------------
// bf16x3 GEMM via mma.sync: D[m,n] = sum_k A[m,k]*B[n,k].  BM=128, BK=64.
// ASPLIT: A is fp32 and is split into bf16 hi/lo during smem staging.
// OUTMODE: 0 = fp32, 1 = fp32 + rel-bias (raw logits), 2 = bf16 hi/lo pair.
// ---------------------------------------------------------------------------
template<int BN, bool ASPLIT, int OUTMODE>
__global__ void __launch_bounds__(256, 1) gemm3_kernel(
    const __nv_bfloat16* __restrict__ Ahi_g, const __nv_bfloat16* __restrict__ Alo_g,
    const float* __restrict__ Af_g, int lda, long long sAb, long long sAh,
    const __nv_bfloat16* __restrict__ Bhi_g, const __nv_bfloat16* __restrict__ Blo_g,
    int ldb, long long sBb, long long sBh,
    float* __restrict__ Cf, __nv_bfloat16* __restrict__ Chi, __nv_bfloat16* __restrict__ Clo,
    int ldc, long long sCb, long long sCh, int K)
{
    extern __shared__ char smem[];
    __shared__ float bias_sm[256];

    const int tid = threadIdx.x, wid = tid >> 5, lane = tid & 31;
    const int zb = blockIdx.z >> 4, zh = blockIdx.z & 15;
    const int m0 = blockIdx.y * 128, n0 = blockIdx.x * BN;

    constexpr int A_BYTES = 128 * SA * 2;          // one A matrix (hi or lo)
    constexpr int B_BYTES = BN * SA * 2;
    constexpr int STAGE   = 2*A_BYTES + 2*B_BYTES; // Ahi,Alo,Bhi,Blo
    const uint32_t smb = smem_u32(smem);

    if (OUTMODE == 1 && tid < 255)
        bias_sm[tid] = g_bias[zh*kNB + n0 - m0 + 1920 + tid];

    const __nv_bfloat16* Ah = Ahi_g + zb*sAb + zh*sAh;
    const __nv_bfloat16* Al = Alo_g + zb*sAb + zh*sAh;
    const float*         Af = Af_g  + zb*sAb + zh*sAh;
    const __nv_bfloat16* Bh = Bhi_g + zb*sBb + zh*sBh;
    const __nv_bfloat16* Bl = Blo_g + zb*sBb + zh*sBh;

    const int T = K >> 6;

    auto issue = [&](int t){
        const int s = t & 1, k0 = t << 6;
        const uint32_t stA_hi = smb + s*STAGE;
        const uint32_t stA_lo = stA_hi + A_BYTES;
        const uint32_t stB_hi = stA_hi + 2*A_BYTES;
        const uint32_t stB_lo = stB_hi + B_BYTES;
        if (!ASPLIT){
#pragma unroll
            for (int i = 0; i < 4; i++){
                int u = i*256 + tid, row = u >> 3, c = u & 7;
                size_t so = (size_t)(m0+row)*lda + k0 + c*8;
                uint32_t off = (uint32_t)(row*(SA*2) + c*16);
                cp16(stA_hi + off, Ah + so);
                cp16(stA_lo + off, Al + so);
            }
        } else {
#pragma unroll
            for (int i = 0; i < 8; i++){
                int u = i*256 + tid, row = u >> 4, c4 = u & 15;
                float4 v = *(const float4*)(Af + (size_t)(m0+row)*lda + k0 + c4*4);
                __nv_bfloat162 h0 = __floats2bfloat162_rn(v.x, v.y);
                __nv_bfloat162 h1 = __floats2bfloat162_rn(v.z, v.w);
                __nv_bfloat162 l0 = __floats2bfloat162_rn(v.x - __bfloat162float(h0.x),
                                                          v.y - __bfloat162float(h0.y));
                __nv_bfloat162 l1 = __floats2bfloat162_rn(v.z - __bfloat162float(h1.x),
                                                          v.w - __bfloat162float(h1.y));
                uint32_t off = (uint32_t)(row*(SA*2) + c4*8);
                asm volatile("st.shared.v2.b32 [%0], {%1,%2};"
                             :: "r"(stA_hi + off), "r"(*(uint32_t*)&h0), "r"(*(uint32_t*)&h1) : "memory");
                asm volatile("st.shared.v2.b32 [%0], {%1,%2};"
                             :: "r"(stA_lo + off), "r"(*(uint32_t*)&l0), "r"(*(uint32_t*)&l1) : "memory");
            }
        }
#pragma unroll
        for (int i = 0; i < BN/32; i++){
            int u = i*256 + tid, row = u >> 3, c = u & 7;
            size_t so = (size_t)(n0+row)*ldb + k0 + c*8;
            uint32_t off = (uint32_t)(row*(SA*2) + c*16);
            cp16(stB_hi + off, Bh + so);
            cp16(stB_lo + off, Bl + so);
        }
    };

    constexpr int MF = (BN == 128) ? 4 : 2;         // 16-row m-frags per warp
    const int wm = (BN == 128) ? (wid >> 2)*64 : (wid >> 1)*32;
    const int wn = (BN == 128) ? (wid & 3)*32  : (wid & 1)*32;

    // per-thread ldmatrix byte offsets (within a matrix)
    const uint32_t a_off = (uint32_t)((wm + (lane & 15))*(SA*2) + (lane >> 4)*16);
    const uint32_t b_off = (uint32_t)((wn + ((lane >> 4) << 3) + (lane & 7))*(SA*2)
                                      + ((lane >> 3) & 1)*16);
    float acc[MF][4][4];
#pragma unroll
    for (int i = 0; i < MF; i++)
#pragma unroll
        for (int j = 0; j < 4; j++)
#pragma unroll
            for (int e = 0; e < 4; e++) acc[i][j][e] = 0.0f;

    issue(0);
    cp_commit();

    for (int t = 0; t < T; t++){
        if (t + 1 < T){ issue(t+1); cp_commit(); cp_wait<1>(); }
        else          { cp_wait<0>(); }
        __syncthreads();

        const int s = t & 1;
        const uint32_t stA_hi = smb + s*STAGE;
        const uint32_t stA_lo = stA_hi + A_BYTES;
        const uint32_t stB_hi = stA_hi + 2*A_BYTES;
        const uint32_t stB_lo = stB_hi + B_BYTES;

#pragma unroll
        for (int kk = 0; kk < 4; kk++){
            uint32_t ah[MF][4], al[MF][4], bh[2][4], bl[2][4];
            const uint32_t kb = kk*32;   // 16 bf16 = 32 bytes
#pragma unroll
            for (int i = 0; i < MF; i++){
                ldsm4(ah[i], stA_hi + a_off + i*16*(SA*2) + kb);
                ldsm4(al[i], stA_lo + a_off + i*16*(SA*2) + kb);
            }
#pragma unroll
            for (int j2 = 0; j2 < 2; j2++){
                ldsm4(bh[j2], stB_hi + b_off + j2*16*(SA*2) + kb);
                ldsm4(bl[j2], stB_lo + b_off + j2*16*(SA*2) + kb);
            }
#pragma unroll
            for (int i = 0; i < MF; i++)
#pragma unroll
                for (int j = 0; j < 4; j++){
                    const uint32_t* Bh2 = &bh[j >> 1][(j & 1)*2];
                    const uint32_t* Bl2 = &bl[j >> 1][(j & 1)*2];
                    mma16816(acc[i][j], ah[i], Bh2);
                    mma16816(acc[i][j], ah[i], Bl2);
                    mma16816(acc[i][j], al[i], Bh2);
                }
        }
        __syncthreads();
    }

    // ---- epilogue: regs -> swizzled fp32 smem tile -> coalesced stores
    float* ft = (float*)smem;
    const int q = lane >> 2, nn0 = (lane & 3)*2;
#pragma unroll
    for (int i = 0; i < MF; i++)
#pragma unroll
        for (int j = 0; j < 4; j++){
            int n = wn + j*8 + nn0;
            int C4 = n >> 2, half = (n >> 1) & 1;
            int r0 = wm + i*16 + q, r1 = r0 + 8;
            *(float2*)&ft[r0*BN + ((C4 ^ (r0 & 7)) << 2) + half*2] =
                make_float2(acc[i][j][0], acc[i][j][1]);
            *(float2*)&ft[r1*BN + ((C4 ^ (r1 & 7)) << 2) + half*2] =
                make_float2(acc[i][j][2], acc[i][j][3]);
        }
    __syncthreads();

    const long long offC = zb*sCb + zh*sCh;
    constexpr int RW = BN / 4;
    constexpr int ITER = 128 * RW / 256;
#pragma unroll
    for (int i = 0; i < ITER; i++){
        int u = i*256 + tid;
        int rr = u / RW, C4 = u % RW;
        int C4s = C4 ^ (rr & 7);
        float4 v = *(const float4*)&ft[rr*BN + C4s*4];
        const size_t co = (size_t)offC + (size_t)(m0+rr)*ldc + n0 + C4*4;
        if (OUTMODE == 0){
            *(float4*)(Cf + co) = v;
        } else if (OUTMODE == 1){
            int bi = C4*4 - rr + 127;
            v.x += bias_sm[bi];   v.y += bias_sm[bi+1];
            v.z += bias_sm[bi+2]; v.w += bias_sm[bi+3];
            *(float4*)(Cf + co) = v;
        } else {
            __nv_bfloat162 h0 = __floats2bfloat162_rn(v.x, v.y);
            __nv_bfloat162 h1 = __floats2bfloat162_rn(v.z, v.w);
            __nv_bfloat162 l0 = __floats2bfloat162_rn(v.x - __bfloat162float(h0.x),
                                                      v.y - __bfloat162float(h0.y));
            __nv_bfloat162 l1 = __floats2bfloat162_rn(v.z - __bfloat162float(h1.x),
                                                      v.w - __bfloat162float(h1.y));
            *(uint2*)(Chi + co) = make_uint2(*(uint32_t*)&h0, *(uint32_t*)&h1);
            *(uint2*)(Clo + co) = make_uint2(*(uint32_t*)&l0, *(uint32_t*)&l1);
        }
    }
}

// ---------------------------------------------------------------------------
extern "C" void kernel_launch(void* const* d_in, const int* in_sizes, int n_in,
                              void* d_out, int out_size) {
    const float* hidden = (const float*)d_in[0];
    const float* wq = (const float*)d_in[1];
    const float* wk = (const float*)d_in[2];
    const float* wv = (const float*)d_in[3];
    const float* wo = (const float*)d_in[4];
    const float* rb = (const float*)d_in[5];
    float* out  = (float*)d_out;
    float* attn = out + kOUT0;

    #define SYM(p, s) void* p; cudaGetSymbolAddress(&p, s)
    SYM(xhi, g_xhi); SYM(xlo, g_xlo);
    SYM(wqhi, g_wqhi); SYM(wqlo, g_wqlo);
    SYM(wkhi, g_wkhi); SYM(wklo, g_wklo);
    SYM(wvhi, g_wvhi); SYM(wvlo, g_wvlo);
    SYM(wohi, g_wohi); SYM(wolo, g_wolo);
    SYM(qhi, g_qhi); SYM(qlo, g_qlo);
    SYM(khi, g_khi); SYM(klo, g_klo);
    SYM(vhi, g_vhi); SYM(vlo, g_vlo);
    SYM(vthi, g_vthi); SYM(vtlo, g_vtlo);
    SYM(chi, g_chi); SYM(clo, g_clo);
    #undef SYM
    typedef const __nv_bfloat16* BF;
    typedef __nv_bfloat16* BFm;

    auto proj = gemm3_kernel<128, false, 2>;
    auto qkg  = gemm3_kernel<128, false, 1>;
    auto pvg  = gemm3_kernel<64,  true,  2>;
    auto outg = gemm3_kernel<128, false, 0>;
    // smem: BN=128 stage = 2*(2*128*88*2) = 90112 B -> 180224; BN=64 -> 135168
    cudaFuncSetAttribute(proj, cudaFuncAttributeMaxDynamicSharedMemorySize, 180224);
    cudaFuncSetAttribute(qkg,  cudaFuncAttributeMaxDynamicSharedMemorySize, 180224);
    cudaFuncSetAttribute(outg, cudaFuncAttributeMaxDynamicSharedMemorySize, 180224);
    cudaFuncSetAttribute(pvg,  cudaFuncAttributeMaxDynamicSharedMemorySize, 135168);

    bias_kernel<<<(kH*kNB + 255)/256, 256>>>(rb);
    convert_x_kernel<<<kM*kD/256, 256>>>(hidden);
    dim3 tb(32, 8);
    transpose_split_kernel<<<dim3(32, 32), tb>>>(wq, (BFm)wqhi, (BFm)wqlo);
    transpose_split_kernel<<<dim3(32, 32), tb>>>(wk, (BFm)wkhi, (BFm)wklo);
    transpose_split_kernel<<<dim3(32, 32), tb>>>(wv, (BFm)wvhi, (BFm)wvlo);
    transpose_split_kernel<<<dim3(32, 32), tb>>>(wo, (BFm)wohi, (BFm)wolo);

    // projections: [4096,1024] = X * W^T(pair), bf16 pair out, row-major
    proj<<<dim3(8, 32, 1), 256, 180224>>>(
        (BF)xhi, (BF)xlo, nullptr, kD, 0, 0,
        (BF)wqhi, (BF)wqlo, kD, 0, 0,
        nullptr, (BFm)qhi, (BFm)qlo, kD, 0, 0, kD);
    proj<<<dim3(8, 32, 1), 256, 180224>>>(
        (BF)xhi, (BF)xlo, nullptr, kD, 0, 0,
        (BF)wkhi, (BF)wklo, kD, 0, 0,
        nullptr, (BFm)khi, (BFm)klo, kD, 0, 0, kD);
    proj<<<dim3(8, 32, 1), 256, 180224>>>(
        (BF)xhi, (BF)xlo, nullptr, kD, 0, 0,
        (BF)wvhi, (BF)wvlo, kD, 0, 0,
        nullptr, (BFm)vhi, (BFm)vlo, kD, 0, 0, kD);

    transpose_v_kernel<<<dim3(64, 2, 32), tb>>>();

    // raw logits: attn[z] = Q_z K_z^T + bias
    qkg<<<dim3(16, 16, 32), 256, 180224>>>(
        (BF)qhi, (BF)qlo, nullptr, kD, 2097152LL, 64LL,
        (BF)khi, (BF)klo, kD, 2097152LL, 64LL,
        attn, nullptr, nullptr, kS, 67108864LL, 4194304LL, kDK);

    softmax_kernel<<<kBH*kS, 256>>>(attn);

    // ctx pair = attn(z) * Vt(z)^T : A fp32-split, BN=64
    pvg<<<dim3(1, 16, 32), 256, 135168>>>(
        nullptr, nullptr, attn, kS, 67108864LL, 4194304LL,
        (BF)vthi, (BF)vtlo, kS, 2097152LL, 131072LL,
        nullptr, (BFm)chi, (BFm)clo, kD, 2097152LL, 64LL, kS);

    // attn_output = ctx * Wo^T(pair), fp32
    outg<<<dim3(8, 32, 1), 256, 180224>>>(
        (BF)chi, (BF)clo, nullptr, kD, 0, 0,
        (BF)wohi, (BF)wolo, kD, 0, 0,
        out, nullptr, nullptr, kD, 0, 0, kD);
}